// round 7
// baseline (speedup 1.0000x reference)
#include <cuda_runtime.h>
#include <math.h>

#define NN   50000
#define EE   100000
#define GG   2048

typedef unsigned long long ull;

// ---------------- device scratch ----------------
__device__ float g_h[NN * 32];
__device__ float g_aggr[NN * 32];
__device__ float g_Y[NN * 160];      // [node][j*32+o], j=0..3 feat mats, j=4 bias mat
__device__ float g_pool[GG * 32];
__device__ float g_cnt[GG];

// transposed weight tables (input-dim k major, output minor)
__device__ float W_G[64 * 96];       // [k][g]: k<32 -> wi[g][k], k>=32 -> wh[g][k-32]
__device__ float W_MS[32 * 160];     // [k][j*32+o]

// ---------------- f32x2 helpers ----------------
__device__ __forceinline__ ull ffma2(ull a, ull b, ull c) {
    ull d;
    asm("fma.rn.f32x2 %0, %1, %2, %3;" : "=l"(d) : "l"(a), "l"(b), "l"(c));
    return d;
}
__device__ __forceinline__ ull dup2(float w) {
    ull r;
    asm("mov.b64 %0, {%1, %1};" : "=l"(r) : "f"(w));
    return r;
}
__device__ __forceinline__ float flo(ull v) { return __uint_as_float((unsigned)v); }
__device__ __forceinline__ float fhi(ull v) { return __uint_as_float((unsigned)(v >> 32)); }

// ---------------- K_pack: zero pool + build transposed weights ----------------
__global__ void k_pack(const float* __restrict__ wi,     // [96,32]
                       const float* __restrict__ wh,     // [96,32]
                       const float* __restrict__ nn_w,   // [1024,4]
                       const float* __restrict__ nn_b) { // [1024]
    int gid = blockIdx.x * blockDim.x + threadIdx.x;
    if (gid < GG * 32) g_pool[gid] = 0.0f;
    if (gid < GG) g_cnt[gid] = 0.0f;

    if (gid < 64 * 96) {            // W_G
        int k = gid / 96, g = gid % 96;
        W_G[gid] = (k < 32) ? wi[g * 32 + k] : wh[g * 32 + (k - 32)];
    }
    if (gid < 32 * 160) {           // W_MS
        int k = gid / 160, jo = gid % 160;
        int j = jo >> 5, o = jo & 31;
        W_MS[gid] = (j < 4) ? nn_w[(k * 32 + o) * 4 + j] : nn_b[k * 32 + o];
    }
}

// ============= Y stage (shared between k_init and k_node) =============
// sh rows [rowoff .. rowoff+31] hold h k-major: sh[rowoff+k][col] = h[node col][k]
#define Y_STAGE_AND_STORE(SH, ROWOFF, COLBASE, N0, LANE)                        \
    do {                                                                        \
        ull Yk[4][5];                                                           \
        _Pragma("unroll")                                                       \
        for (int q = 0; q < 4; q++)                                             \
            _Pragma("unroll")                                                   \
            for (int j = 0; j < 5; j++) Yk[q][j] = 0ull;                        \
        _Pragma("unroll 8")                                                     \
        for (int k = 0; k < 32; k++) {                                          \
            ulonglong2 o01 = *(const ulonglong2*)&SH[(ROWOFF) + k][(COLBASE)];  \
            ulonglong2 o23 = *(const ulonglong2*)&SH[(ROWOFF) + k][(COLBASE) + 4]; \
            _Pragma("unroll")                                                   \
            for (int j = 0; j < 5; j++) {                                       \
                ull w2 = dup2(__ldg(&W_MS[k * 160 + j * 32 + (LANE)]));         \
                Yk[0][j] = ffma2(o01.x, w2, Yk[0][j]);                          \
                Yk[1][j] = ffma2(o01.y, w2, Yk[1][j]);                          \
                Yk[2][j] = ffma2(o23.x, w2, Yk[2][j]);                          \
                Yk[3][j] = ffma2(o23.y, w2, Yk[3][j]);                          \
            }                                                                   \
        }                                                                       \
        _Pragma("unroll")                                                       \
        for (int n = 0; n < 8; n++) {                                           \
            int node = (N0) + n;                                                \
            if (node < NN) {                                                    \
                _Pragma("unroll")                                               \
                for (int j = 0; j < 5; j++) {                                   \
                    float v = (n & 1) ? fhi(Yk[n >> 1][j]) : flo(Yk[n >> 1][j]); \
                    g_Y[(size_t)node * 160 + j * 32 + (LANE)] = v;              \
                }                                                               \
            }                                                                   \
        }                                                                       \
    } while (0)

// ---------------- K_init: h0 = relu(lin0); Y0; zero aggr ----------------
// 8 warps x 8 nodes = 64 nodes/block; lane = output dim
__global__ __launch_bounds__(256, 2) void k_init(const float* __restrict__ x,
                                                 const float* __restrict__ w,   // [32,11]
                                                 const float* __restrict__ b) { // [32]
    __shared__ __align__(16) float sh[32][68];
    int t = threadIdx.x, wrp = t >> 5, lane = t & 31;
    int n0 = blockIdx.x * 64 + wrp * 8;
    int colbase = wrp * 8;

    float bias = __ldg(&b[lane]);
    float wv[11];
#pragma unroll
    for (int f = 0; f < 11; f++) wv[f] = __ldg(&w[lane * 11 + f]);

    float hreg[8];
#pragma unroll
    for (int n = 0; n < 8; n++) {
        int node = n0 + n;
        float s = bias;
        if (node < NN) {
#pragma unroll
            for (int f = 0; f < 11; f++) s += __ldg(&x[node * 11 + f]) * wv[f];
        }
        hreg[n] = fmaxf(s, 0.0f);
        sh[lane][colbase + n] = hreg[n];       // transpose store: row=k(=lane), col=node
    }
    __syncwarp();

#pragma unroll
    for (int n = 0; n < 8; n++) {
        int node = n0 + n;
        if (node < NN) {
            g_h[node * 32 + lane] = hreg[n];
            g_aggr[node * 32 + lane] = 0.0f;
        }
    }

    Y_STAGE_AND_STORE(sh, 0, colbase, n0, lane);
}

// ---------------- K_edge: 2 edges per warp, batched gathers + scatter-add ----------------
__global__ void k_edge(const int* __restrict__ ei,        // [2,E]
                       const float* __restrict__ ea) {    // [E,4]
    int gt   = blockIdx.x * blockDim.x + threadIdx.x;
    int wrp  = gt >> 5;
    int lane = gt & 31;
    int e0   = wrp * 2;
    if (e0 >= EE) return;

    int s0 = __ldg(&ei[e0]);
    int d0 = __ldg(&ei[EE + e0]);
    float4 a0 = __ldg(&reinterpret_cast<const float4*>(ea)[e0]);
    const float* yb0 = &g_Y[(size_t)s0 * 160];

    bool has1 = (e0 + 1) < EE;
    int s1 = has1 ? __ldg(&ei[e0 + 1]) : s0;
    int d1 = has1 ? __ldg(&ei[EE + e0 + 1]) : d0;
    float4 a1 = has1 ? __ldg(&reinterpret_cast<const float4*>(ea)[e0 + 1]) : a0;
    const float* yb1 = &g_Y[(size_t)s1 * 160];

    float v0b = __ldg(&yb0[128 + lane]);
    float v00 = __ldg(&yb0[0   + lane]);
    float v01 = __ldg(&yb0[32  + lane]);
    float v02 = __ldg(&yb0[64  + lane]);
    float v03 = __ldg(&yb0[96  + lane]);
    float v1b = __ldg(&yb1[128 + lane]);
    float v10 = __ldg(&yb1[0   + lane]);
    float v11 = __ldg(&yb1[32  + lane]);
    float v12 = __ldg(&yb1[64  + lane]);
    float v13 = __ldg(&yb1[96  + lane]);

    float m0 = v0b + a0.x * v00 + a0.y * v01 + a0.z * v02 + a0.w * v03;
    atomicAdd(&g_aggr[d0 * 32 + lane], m0);
    if (has1) {
        float m1 = v1b + a1.x * v10 + a1.y * v11 + a1.z * v12 + a1.w * v13;
        atomicAdd(&g_aggr[d1 * 32 + lane], m1);
    }
}

// ---------------- K_node: root matvec + fused GRU + next-round Y (or pooling) ----------------
// 8 warps x 8 nodes = 64 nodes/block; lane = output dim.
// sh rows 0-31 = m (k-major), rows 32-63 = h (k-major).
__global__ __launch_bounds__(256, 2) void k_node(const float* __restrict__ root_w, // [32,32]
                                                 const float* __restrict__ conv_b, // [32]
                                                 const float* __restrict__ bi,     // [96]
                                                 const float* __restrict__ bh,     // [96]
                                                 const int* __restrict__ batch,
                                                 int last) {
    __shared__ __align__(16) float sh[64][68];
    int t = threadIdx.x, wrp = t >> 5, lane = t & 31;
    int n0 = blockIdx.x * 64 + wrp * 8;
    int colbase = wrp * 8;

    // stage h (k-major) + keep in registers; prefetch aggr
    float hreg[8], areg[8];
#pragma unroll
    for (int n = 0; n < 8; n++) {
        int node = n0 + n;
        hreg[n] = (node < NN) ? g_h[node * 32 + lane] : 0.0f;
        sh[32 + lane][colbase + n] = hreg[n];
    }
#pragma unroll
    for (int n = 0; n < 8; n++) {
        int node = n0 + n;
        areg[n] = (node < NN) ? __ldg(&g_aggr[node * 32 + lane]) : 0.0f;
    }
    __syncwarp();

    // --- root matvec: R[o=lane] = sum_k h[k]*root_w[k][o] ---
    ull R[4];
#pragma unroll
    for (int q = 0; q < 4; q++) R[q] = 0ull;
#pragma unroll 8
    for (int k = 0; k < 32; k++) {
        ulonglong2 o01 = *(const ulonglong2*)&sh[32 + k][colbase];
        ulonglong2 o23 = *(const ulonglong2*)&sh[32 + k][colbase + 4];
        ull w2 = dup2(__ldg(&root_w[k * 32 + lane]));
        R[0] = ffma2(o01.x, w2, R[0]);
        R[1] = ffma2(o01.y, w2, R[1]);
        R[2] = ffma2(o23.x, w2, R[2]);
        R[3] = ffma2(o23.y, w2, R[3]);
    }
    float cb = __ldg(&conv_b[lane]);
#pragma unroll
    for (int n = 0; n < 8; n++) {
        float r = (n & 1) ? fhi(R[n >> 1]) : flo(R[n >> 1]);
        float m = fmaxf(r + areg[n] + cb, 0.0f);
        sh[lane][colbase + n] = m;            // m k-major, rows 0-31
        int node = n0 + n;
        if (node < NN) g_aggr[node * 32 + lane] = 0.0f;   // pre-zero for next round
    }
    __syncwarp();

    // --- fused GRU: A=r-gate, B=z-gate, C=inn (m-part), D=hn (h-part) ---
    ull A[4], B[4], C[4], D[4];
#pragma unroll
    for (int q = 0; q < 4; q++) { A[q] = B[q] = C[q] = D[q] = 0ull; }
#pragma unroll 8
    for (int k = 0; k < 32; k++) {            // m rows
        ulonglong2 o01 = *(const ulonglong2*)&sh[k][colbase];
        ulonglong2 o23 = *(const ulonglong2*)&sh[k][colbase + 4];
        ull wr = dup2(__ldg(&W_G[k * 96 + lane]));
        ull wz = dup2(__ldg(&W_G[k * 96 + 32 + lane]));
        ull wn = dup2(__ldg(&W_G[k * 96 + 64 + lane]));
        A[0] = ffma2(o01.x, wr, A[0]); A[1] = ffma2(o01.y, wr, A[1]);
        A[2] = ffma2(o23.x, wr, A[2]); A[3] = ffma2(o23.y, wr, A[3]);
        B[0] = ffma2(o01.x, wz, B[0]); B[1] = ffma2(o01.y, wz, B[1]);
        B[2] = ffma2(o23.x, wz, B[2]); B[3] = ffma2(o23.y, wz, B[3]);
        C[0] = ffma2(o01.x, wn, C[0]); C[1] = ffma2(o01.y, wn, C[1]);
        C[2] = ffma2(o23.x, wn, C[2]); C[3] = ffma2(o23.y, wn, C[3]);
    }
#pragma unroll 8
    for (int k = 32; k < 64; k++) {           // h rows
        ulonglong2 o01 = *(const ulonglong2*)&sh[k][colbase];
        ulonglong2 o23 = *(const ulonglong2*)&sh[k][colbase + 4];
        ull wr = dup2(__ldg(&W_G[k * 96 + lane]));
        ull wz = dup2(__ldg(&W_G[k * 96 + 32 + lane]));
        ull wn = dup2(__ldg(&W_G[k * 96 + 64 + lane]));
        A[0] = ffma2(o01.x, wr, A[0]); A[1] = ffma2(o01.y, wr, A[1]);
        A[2] = ffma2(o23.x, wr, A[2]); A[3] = ffma2(o23.y, wr, A[3]);
        B[0] = ffma2(o01.x, wz, B[0]); B[1] = ffma2(o01.y, wz, B[1]);
        B[2] = ffma2(o23.x, wz, B[2]); B[3] = ffma2(o23.y, wz, B[3]);
        D[0] = ffma2(o01.x, wn, D[0]); D[1] = ffma2(o01.y, wn, D[1]);
        D[2] = ffma2(o23.x, wn, D[2]); D[3] = ffma2(o23.y, wn, D[3]);
    }

    float bir = __ldg(&bi[lane]), biz = __ldg(&bi[lane + 32]), bin = __ldg(&bi[lane + 64]);
    float bhr = __ldg(&bh[lane]), bhz = __ldg(&bh[lane + 32]), bhn = __ldg(&bh[lane + 64]);

    float hn[8];
#pragma unroll
    for (int n = 0; n < 8; n++) {
        int q = n >> 1;
        float ga = (n & 1) ? fhi(A[q]) : flo(A[q]);
        float gb = (n & 1) ? fhi(B[q]) : flo(B[q]);
        float gc = (n & 1) ? fhi(C[q]) : flo(C[q]);
        float gd = (n & 1) ? fhi(D[q]) : flo(D[q]);
        float r  = 1.0f / (1.0f + __expf(-(ga + bir + bhr)));
        float z  = 1.0f / (1.0f + __expf(-(gb + biz + bhz)));
        float nv = tanhf(gc + bin + r * (gd + bhn));
        hn[n] = (1.0f - z) * nv + z * hreg[n];
    }

    if (last) {
#pragma unroll
        for (int n = 0; n < 8; n++) {
            int node = n0 + n;
            if (node < NN) {
                int bg = __ldg(&batch[node]);
                atomicAdd(&g_pool[bg * 32 + lane], hn[n]);
                if (lane == 0) atomicAdd(&g_cnt[bg], 1.0f);
            }
        }
        return;
    }

    // overwrite h rows with hn, store g_h
#pragma unroll
    for (int n = 0; n < 8; n++) {
        sh[32 + lane][colbase + n] = hn[n];
        int node = n0 + n;
        if (node < NN) g_h[node * 32 + lane] = hn[n];
    }
    __syncwarp();

    Y_STAGE_AND_STORE(sh, 32, colbase, n0, lane);
}

// ---------------- K_final: logits + log_softmax ----------------
__global__ void k_final(const float* __restrict__ w,   // [2,32]
                        const float* __restrict__ b,   // [2]
                        float* __restrict__ out) {     // [G,2]
    int g = blockIdx.x * blockDim.x + threadIdx.x;
    if (g >= GG) return;
    float inv = 1.0f / fmaxf(g_cnt[g], 1.0f);
    float l0 = b[0], l1 = b[1];
#pragma unroll
    for (int d = 0; d < 32; d++) {
        float p = g_pool[g * 32 + d] * inv;
        l0 += p * w[d];
        l1 += p * w[32 + d];
    }
    float mx  = fmaxf(l0, l1);
    float lse = mx + logf(__expf(l0 - mx) + __expf(l1 - mx));
    out[g * 2 + 0] = l0 - lse;
    out[g * 2 + 1] = l1 - lse;
}

// ---------------- launch ----------------
extern "C" void kernel_launch(void* const* d_in, const int* in_sizes, int n_in,
                              void* d_out, int out_size) {
    const float* x        = (const float*)d_in[0];
    const float* edge_attr= (const float*)d_in[1];
    const float* lin0_w   = (const float*)d_in[2];
    const float* lin0_b   = (const float*)d_in[3];
    const float* nn_w     = (const float*)d_in[4];
    const float* nn_b     = (const float*)d_in[5];
    const float* root_w   = (const float*)d_in[6];
    const float* conv_b   = (const float*)d_in[7];
    const float* gru_wi   = (const float*)d_in[8];
    const float* gru_wh   = (const float*)d_in[9];
    const float* gru_bi   = (const float*)d_in[10];
    const float* gru_bh   = (const float*)d_in[11];
    const float* lin1_w   = (const float*)d_in[12];
    const float* lin1_b   = (const float*)d_in[13];
    const int*   edge_idx = (const int*)d_in[14];
    const int*   batch    = (const int*)d_in[15];
    float* out = (float*)d_out;

    const int TPB = 256;
    const int nodeBlocks = (NN + 63) / 64;                           // 782
    const int edgeWarpBlocks = ((EE + 1) / 2 * 32 + TPB - 1) / TPB;  // 6250
    const int packBlocks = (GG * 32 + TPB - 1) / TPB;                // 256

    k_pack<<<packBlocks, TPB>>>(gru_wi, gru_wh, nn_w, nn_b);
    k_init<<<nodeBlocks, TPB>>>(x, lin0_w, lin0_b);

    for (int round = 0; round < 3; round++) {
        k_edge<<<edgeWarpBlocks, TPB>>>(edge_idx, edge_attr);
        k_node<<<nodeBlocks, TPB>>>(root_w, conv_b, gru_bi, gru_bh, batch, round == 2);
    }

    k_final<<<(GG + TPB - 1) / TPB, TPB>>>(lin1_w, lin1_b, out);
}